// round 1
// baseline (speedup 1.0000x reference)
#include <cuda_runtime.h>
#include <cuda_bf16.h>
#include <cstdint>

// Problem dims (fixed for this instance)
static constexpr int MAX_M = 8192;
static constexpr int MAX_K = 4096;
static constexpr int MAX_N = 11008;

// Scratch: split bf16 hi/lo copies of X and Weff (W + 2*B@A folded in fp32)
__device__ __nv_bfloat16 g_Xh[(size_t)MAX_M * MAX_K];
__device__ __nv_bfloat16 g_Xl[(size_t)MAX_M * MAX_K];
__device__ __nv_bfloat16 g_Wh[(size_t)MAX_N * MAX_K];
__device__ __nv_bfloat16 g_Wl[(size_t)MAX_N * MAX_K];

// ---------------------------------------------------------------------------
// Prologue 1: split X into bf16 hi/lo
// ---------------------------------------------------------------------------
__global__ void split_x_kernel(const float4* __restrict__ X, size_t n4) {
    size_t i = (size_t)blockIdx.x * blockDim.x + threadIdx.x;
    if (i >= n4) return;
    float4 v = X[i];
    __nv_bfloat16 hx = __float2bfloat16(v.x);
    __nv_bfloat16 hy = __float2bfloat16(v.y);
    __nv_bfloat16 hz = __float2bfloat16(v.z);
    __nv_bfloat16 hw = __float2bfloat16(v.w);
    __nv_bfloat16 lx = __float2bfloat16(v.x - __bfloat162float(hx));
    __nv_bfloat16 ly = __float2bfloat16(v.y - __bfloat162float(hy));
    __nv_bfloat16 lz = __float2bfloat16(v.z - __bfloat162float(hz));
    __nv_bfloat16 lw = __float2bfloat16(v.w - __bfloat162float(hw));
    __nv_bfloat162* Xh2 = reinterpret_cast<__nv_bfloat162*>(g_Xh);
    __nv_bfloat162* Xl2 = reinterpret_cast<__nv_bfloat162*>(g_Xl);
    Xh2[2 * i]     = __halves2bfloat162(hx, hy);
    Xh2[2 * i + 1] = __halves2bfloat162(hz, hw);
    Xl2[2 * i]     = __halves2bfloat162(lx, ly);
    Xl2[2 * i + 1] = __halves2bfloat162(lz, lw);
}

// ---------------------------------------------------------------------------
// Prologue 2: Weff = W + 2.0*(B@A), split into bf16 hi/lo
// Block: 32 output rows x 512 input cols, A-slab and B-slab staged in smem.
// ---------------------------------------------------------------------------
static constexpr int FO = 32;   // out-rows per block
static constexpr int FI = 512;  // in-cols per block

__global__ void fold_w_kernel(const float* __restrict__ W,
                              const float* __restrict__ Bm,  // [N,16]
                              const float* __restrict__ Am,  // [16,K]
                              int N, int K) {
    __shared__ float sA[16][FI];
    __shared__ float sB[FO][16];
    const int iBase = blockIdx.x * FI;
    const int oBase = blockIdx.y * FO;
    const int tid = threadIdx.x;  // 256 threads

    for (int j = tid; j < 16 * FI; j += 256) {
        int r = j / FI, i = j % FI;
        sA[r][i] = Am[(size_t)r * K + iBase + i];
    }
    for (int j = tid; j < FO * 16; j += 256) {
        int o = j / 16, r = j % 16;
        sB[o][r] = Bm[(size_t)(oBase + o) * 16 + r];
    }
    __syncthreads();

    #pragma unroll 4
    for (int e = 0; e < (FO * FI) / 256; e++) {
        int idx = tid + 256 * e;
        int oo = idx / FI, ii = idx % FI;
        size_t g = (size_t)(oBase + oo) * K + iBase + ii;
        float acc = W[g];
        #pragma unroll
        for (int r = 0; r < 16; r++)
            acc += 2.0f * sB[oo][r] * sA[r][ii];
        __nv_bfloat16 h = __float2bfloat16(acc);
        g_Wh[g] = h;
        g_Wl[g] = __float2bfloat16(acc - __bfloat162float(h));
    }
}

// ---------------------------------------------------------------------------
// Main GEMM: C = Xh@Wh^T + Xh@Wl^T + Xl@Wh^T + bias   (bf16x3 ~ fp32 accuracy)
// CTA tile 128x128xK, BK=32, 8 warps (2x4), warp tile 64x32, mma.m16n8k16.
// ---------------------------------------------------------------------------
static constexpr int BM = 128, BN = 128, BK = 32;
static constexpr int LDT = BK + 8;                 // padded bf16 row (conflict-free)
static constexpr int TILE_ELEMS = BM * LDT;        // 5120 bf16 per operand tile
static constexpr int STAGE_ELEMS = 4 * TILE_ELEMS; // xh,xl,wh,wl
static constexpr int SMEM_BYTES = 2 * STAGE_ELEMS * (int)sizeof(__nv_bfloat16); // 81920

#define MMA_BF16(d, a, b)                                                      \
    asm volatile(                                                              \
        "mma.sync.aligned.m16n8k16.row.col.f32.bf16.bf16.f32 "                 \
        "{%0,%1,%2,%3}, {%4,%5,%6,%7}, {%8,%9}, {%0,%1,%2,%3};"                \
        : "+f"((d)[0]), "+f"((d)[1]), "+f"((d)[2]), "+f"((d)[3])               \
        : "r"((a)[0]), "r"((a)[1]), "r"((a)[2]), "r"((a)[3]),                  \
          "r"((b)[0]), "r"((b)[1]))

__device__ __forceinline__ void issue_stage(__nv_bfloat16* st, int k0,
                                            int mBase, int nBase, int K, int tid) {
    const __nv_bfloat16* srcs[4] = {
        g_Xh + (size_t)mBase * K, g_Xl + (size_t)mBase * K,
        g_Wh + (size_t)nBase * K, g_Wl + (size_t)nBase * K};
    #pragma unroll
    for (int j = 0; j < 8; j++) {
        int c = tid + 256 * j;       // 0..2047 16B chunks
        int t4 = c >> 9;             // which operand tile
        int idx = c & 511;
        int row = idx >> 2;
        int col16 = idx & 3;         // 8-elem (16B) column group
        const __nv_bfloat16* g = srcs[t4] + (size_t)row * K + k0 + col16 * 8;
        __nv_bfloat16* sdst = st + t4 * TILE_ELEMS + row * LDT + col16 * 8;
        uint32_t sa = (uint32_t)__cvta_generic_to_shared(sdst);
        asm volatile("cp.async.cg.shared.global [%0], [%1], 16;\n" ::"r"(sa), "l"(g));
    }
    asm volatile("cp.async.commit_group;\n");
}

__device__ __forceinline__ void compute_stage(const __nv_bfloat16* st, int wm, int wn,
                                              int lane, float acc[4][4][4]) {
    const __nv_bfloat16* Xhs = st;
    const __nv_bfloat16* Xls = st + TILE_ELEMS;
    const __nv_bfloat16* Whs = st + 2 * TILE_ELEMS;
    const __nv_bfloat16* Wls = st + 3 * TILE_ELEMS;
    const int qrow = lane >> 2;
    const int qk = (lane & 3) * 2;
    #pragma unroll
    for (int kk = 0; kk < 2; kk++) {
        const int kb = kk * 16 + qk;
        uint32_t bh[4][2], bl[4][2];
        #pragma unroll
        for (int nt = 0; nt < 4; nt++) {
            int n0 = wn * 32 + nt * 8 + qrow;
            bh[nt][0] = *(const uint32_t*)(Whs + n0 * LDT + kb);
            bh[nt][1] = *(const uint32_t*)(Whs + n0 * LDT + kb + 8);
            bl[nt][0] = *(const uint32_t*)(Wls + n0 * LDT + kb);
            bl[nt][1] = *(const uint32_t*)(Wls + n0 * LDT + kb + 8);
        }
        #pragma unroll
        for (int mt = 0; mt < 4; mt++) {
            int m0 = wm * 64 + mt * 16 + qrow;
            uint32_t ah[4], al[4];
            ah[0] = *(const uint32_t*)(Xhs + m0 * LDT + kb);
            ah[1] = *(const uint32_t*)(Xhs + (m0 + 8) * LDT + kb);
            ah[2] = *(const uint32_t*)(Xhs + m0 * LDT + kb + 8);
            ah[3] = *(const uint32_t*)(Xhs + (m0 + 8) * LDT + kb + 8);
            al[0] = *(const uint32_t*)(Xls + m0 * LDT + kb);
            al[1] = *(const uint32_t*)(Xls + (m0 + 8) * LDT + kb);
            al[2] = *(const uint32_t*)(Xls + m0 * LDT + kb + 8);
            al[3] = *(const uint32_t*)(Xls + (m0 + 8) * LDT + kb + 8);
            #pragma unroll
            for (int nt = 0; nt < 4; nt++) {
                MMA_BF16(acc[mt][nt], ah, bh[nt]);
                MMA_BF16(acc[mt][nt], ah, bl[nt]);
                MMA_BF16(acc[mt][nt], al, bh[nt]);
            }
        }
    }
}

__global__ __launch_bounds__(256, 1)
void gemm_bf16x3_kernel(const float* __restrict__ bias, float* __restrict__ C,
                        int M, int N, int K) {
    extern __shared__ __nv_bfloat16 smem[];
    const int tid = threadIdx.x;
    const int warp = tid >> 5;
    const int lane = tid & 31;
    const int wm = warp >> 2;  // 0..1
    const int wn = warp & 3;   // 0..3
    const int mBase = blockIdx.y * BM;
    const int nBase = blockIdx.x * BN;

    float acc[4][4][4];
    #pragma unroll
    for (int a = 0; a < 4; a++)
        #pragma unroll
        for (int b = 0; b < 4; b++)
            #pragma unroll
            for (int c = 0; c < 4; c++) acc[a][b][c] = 0.0f;

    const int nsteps = K / BK;
    issue_stage(smem, 0, mBase, nBase, K, tid);

    for (int s = 0; s < nsteps; s++) {
        if (s + 1 < nsteps) {
            issue_stage(smem + ((s + 1) & 1) * STAGE_ELEMS, (s + 1) * BK,
                        mBase, nBase, K, tid);
            asm volatile("cp.async.wait_group 1;\n");
        } else {
            asm volatile("cp.async.wait_group 0;\n");
        }
        __syncthreads();
        compute_stage(smem + (s & 1) * STAGE_ELEMS, wm, wn, lane, acc);
        __syncthreads();  // stage buffer reused 2 iterations later
    }

    // Epilogue: add bias, write fp32
    const int qrow = lane >> 2;
    const int qc = (lane & 3) * 2;
    #pragma unroll
    for (int nt = 0; nt < 4; nt++) {
        int col = nBase + wn * 32 + nt * 8 + qc;
        float2 bs = *(const float2*)(bias + col);
        #pragma unroll
        for (int mt = 0; mt < 4; mt++) {
            int row = mBase + wm * 64 + mt * 16 + qrow;
            float2 v0 = make_float2(acc[mt][nt][0] + bs.x, acc[mt][nt][1] + bs.y);
            float2 v1 = make_float2(acc[mt][nt][2] + bs.x, acc[mt][nt][3] + bs.y);
            *(float2*)(C + (size_t)row * N + col) = v0;
            *(float2*)(C + (size_t)(row + 8) * N + col) = v1;
        }
    }
}

// ---------------------------------------------------------------------------
// Launch
// ---------------------------------------------------------------------------
extern "C" void kernel_launch(void* const* d_in, const int* in_sizes, int n_in,
                              void* d_out, int out_size) {
    const float* x    = (const float*)d_in[0];  // [M,K]
    const float* W    = (const float*)d_in[1];  // [N,K]
    const float* bias = (const float*)d_in[2];  // [N]
    const float* B    = (const float*)d_in[3];  // [N,16]
    const float* A    = (const float*)d_in[4];  // [16,K]
    float* out = (float*)d_out;

    const int K = in_sizes[4] / 16;
    const int N = in_sizes[2];
    const int M = in_sizes[0] / K;

    // Prologue: split X, fold LoRA into W and split
    size_t n4 = (size_t)M * K / 4;
    split_x_kernel<<<(unsigned)((n4 + 255) / 256), 256>>>((const float4*)x, n4);
    fold_w_kernel<<<dim3(K / FI, N / FO), 256>>>(W, B, A, N, K);

    // Main GEMM
    cudaFuncSetAttribute(gemm_bf16x3_kernel,
                         cudaFuncAttributeMaxDynamicSharedMemorySize, SMEM_BYTES);
    dim3 grid(N / BN, M / BM);
    gemm_bf16x3_kernel<<<grid, 256, SMEM_BYTES>>>(bias, out, M, N, K);
}